// round 2
// baseline (speedup 1.0000x reference)
#include <cuda_runtime.h>
#include <math.h>

// SRBGCN: 2-layer hyperbolic GCN.
//   per layer: M = LW^T @ LWh (32x32), msg = x @ M, support = adj @ msg,
//   then Minkowski-normalize + selu + Poincare map (fused epilogue).

constexpr int NN = 16384;
constexpr int D  = 32;
constexpr int BM = 64;
constexpr int BK = 32;

// Scratch (static device arrays; no allocation allowed)
__device__ float g_M[D * D];
__device__ float g_msg[NN * D];
__device__ float g_x[NN * D];

// ---------------------------------------------------------------------------
// Kernel 1: build combined transform M[a][b] = sum_c LW[c][a] * LWh[c][b]
//   LW:  block-diag [1 ; W] (W is 31x31)
//   LWh: hyperbolic boost from h (32,)
// One block of 1024 threads; thread (i,j) computes M[i][j].
// ---------------------------------------------------------------------------
__global__ void build_M_kernel(const float* __restrict__ Ws,
                               const float* __restrict__ Hs,
                               int layer) {
    const float* W = Ws + layer * 31 * 31;
    const float* h = Hs + layer * 32;

    __shared__ float LWh[32][32];
    __shared__ float sc[3];  // ch, sh, inv_norm

    int i = threadIdx.x >> 5;
    int j = threadIdx.x & 31;

    if (threadIdx.x == 0) {
        float ss = 0.f;
        for (int t = 1; t < 32; t++) { float v = h[t]; ss += v * v; }
        sc[0] = coshf(h[0]);
        sc[1] = sinhf(h[0]);
        sc[2] = rsqrtf(ss + 1e-14f);
    }
    __syncthreads();

    float ch = sc[0], sh = sc[1], invn = sc[2];
    float ni = (i >= 1) ? h[i] * invn : 0.f;
    float nj = (j >= 1) ? h[j] * invn : 0.f;

    float v;
    if (i == 0 && j == 0)      v = ch;
    else if (i == 0)           v = sh * nj;
    else if (j == 0)           v = sh * ni;
    else                       v = ((i == j) ? 1.f : 0.f) - (1.f - ch) * ni * nj;
    LWh[i][j] = v;
    __syncthreads();

    float m;
    if (i == 0) {
        m = LWh[0][j];
    } else {
        m = 0.f;
        for (int k = 1; k < 32; k++)
            m += W[(k - 1) * 31 + (i - 1)] * LWh[k][j];
    }
    g_M[i * 32 + j] = m;
}

// ---------------------------------------------------------------------------
// Kernel 2: msg = x @ M   (16384x32 @ 32x32) -> g_msg
// One warp per row; lane = output column. x row broadcast via shuffles.
// ---------------------------------------------------------------------------
__global__ void msg_kernel(const float* __restrict__ xin, int use_gx) {
    const float* x = use_gx ? g_x : xin;

    __shared__ float Ms[32 * 32];
    for (int t = threadIdx.x; t < 1024; t += blockDim.x) Ms[t] = g_M[t];
    __syncthreads();

    int gw   = (blockIdx.x * blockDim.x + threadIdx.x) >> 5;
    int lane = threadIdx.x & 31;
    if (gw >= NN) return;

    float xv  = x[(size_t)gw * D + lane];
    float acc = 0.f;
#pragma unroll
    for (int i = 0; i < 32; i++)
        acc = fmaf(__shfl_sync(0xffffffffu, xv, i), Ms[i * 32 + lane], acc);
    g_msg[(size_t)gw * D + lane] = acc;
}

// ---------------------------------------------------------------------------
// Kernel 3: support = adj @ g_msg, fused normalize+selu+Poincare epilogue.
// Block: 128 threads, BM=64 rows, full N=32 cols.
// Thread (tx in [0,8), ty in [0,16)) owns rows {ty,ty+16,ty+32,ty+48},
// cols [tx*4, tx*4+4)  -> 4x4 register tile, 16 FFMA per k per thread.
// ---------------------------------------------------------------------------
__global__ __launch_bounds__(128)
void gemm_epi_kernel(const float* __restrict__ adj,
                     float* __restrict__ outp,
                     int write_gx) {
    __shared__ float adj_s[BM][36];   // pad 4 -> 16B-aligned rows, spread banks
    __shared__ float msg_s[BK][32];

    const int tid  = threadIdx.x;
    const int tx   = tid & 7;
    const int ty   = tid >> 3;
    const int row0 = blockIdx.x * BM;

    float acc[4][4];
#pragma unroll
    for (int i = 0; i < 4; i++)
#pragma unroll
        for (int j = 0; j < 4; j++) acc[i][j] = 0.f;

    for (int kt = 0; kt < NN; kt += BK) {
        // load adj tile (64x32 floats = 512 float4; 4 per thread), coalesced
#pragma unroll
        for (int u = 0; u < 4; u++) {
            int idx = tid + u * 128;            // 0..511
            int r   = idx >> 3;                 // 0..63
            int k4  = idx & 7;                  // float4 index within row
            float4 v = *reinterpret_cast<const float4*>(
                &adj[(size_t)(row0 + r) * NN + kt + k4 * 4]);
            adj_s[r][k4 * 4 + 0] = v.x;
            adj_s[r][k4 * 4 + 1] = v.y;
            adj_s[r][k4 * 4 + 2] = v.z;
            adj_s[r][k4 * 4 + 3] = v.w;
        }
        // load msg tile (32x32 floats = 256 float4; 2 per thread)
#pragma unroll
        for (int u = 0; u < 2; u++) {
            int idx = tid + u * 128;            // 0..255
            int r   = idx >> 3;
            int k4  = idx & 7;
            float4 v = *reinterpret_cast<const float4*>(
                &g_msg[(size_t)(kt + r) * D + k4 * 4]);
            *reinterpret_cast<float4*>(&msg_s[r][k4 * 4]) = v;
        }
        __syncthreads();

#pragma unroll
        for (int k = 0; k < BK; k++) {
            float4 m = *reinterpret_cast<const float4*>(&msg_s[k][tx * 4]);
#pragma unroll
            for (int i = 0; i < 4; i++) {
                float a = adj_s[ty + 16 * i][k];
                acc[i][0] = fmaf(a, m.x, acc[i][0]);
                acc[i][1] = fmaf(a, m.y, acc[i][1]);
                acc[i][2] = fmaf(a, m.z, acc[i][2]);
                acc[i][3] = fmaf(a, m.w, acc[i][3]);
            }
        }
        __syncthreads();
    }

    // stage support rows into shared for the per-row epilogue
#pragma unroll
    for (int i = 0; i < 4; i++)
#pragma unroll
        for (int j = 0; j < 4; j++)
            adj_s[ty + 16 * i][tx * 4 + j] = acc[i][j];
    __syncthreads();

    float* out = write_gx ? g_x : outp;
    const int lane = tid & 31;
    const int w    = tid >> 5;   // 4 warps, 16 rows each

    for (int r = w * 16; r < w * 16 + 16; r++) {
        float s = adj_s[r][lane];

        // minkowski dot: sum(s[1:]^2) - s[0]^2
        float t  = s * s;
        float md = (lane == 0) ? -t : t;
#pragma unroll
        for (int o = 16; o; o >>= 1) md += __shfl_xor_sync(0xffffffffu, md, o);

        float denom = sqrtf(fmaxf(fabsf(md), 1e-8f));
        float xv    = s / denom;
        float x0    = __shfl_sync(0xffffffffu, xv, 0);

        float p = (lane == 0) ? 0.f : xv / (x0 + 1.f);
        // selu
        const float alpha = 1.6732632423543772f;
        const float scale = 1.0507009873554805f;
        p = (p > 0.f) ? scale * p : scale * alpha * (expf(p) - 1.f);

        float pn = p * p;
#pragma unroll
        for (int o = 16; o; o >>= 1) pn += __shfl_xor_sync(0xffffffffu, pn, o);

        float inv  = 1.f / (1.f - pn);
        float outv = (lane == 0) ? (1.f + pn) * inv : 2.f * p * inv;
        out[(size_t)(row0 + r) * D + lane] = outv;
    }
}

// ---------------------------------------------------------------------------
extern "C" void kernel_launch(void* const* d_in, const int* in_sizes, int n_in,
                              void* d_out, int out_size) {
    const float* node = (const float*)d_in[0];  // 16384 x 32
    const float* adj  = (const float*)d_in[1];  // 16384 x 16384
    const float* Ws   = (const float*)d_in[2];  // 2 x 31 x 31
    const float* Hs   = (const float*)d_in[3];  // 2 x 32
    float* out = (float*)d_out;                 // 16384 x 32

    const int msg_blocks  = (NN * 32 + 255) / 256;  // one warp per row, 8/block
    const int gemm_blocks = NN / BM;

    // Layer 0
    build_M_kernel<<<1, 1024>>>(Ws, Hs, 0);
    msg_kernel<<<msg_blocks, 256>>>(node, 0);
    gemm_epi_kernel<<<gemm_blocks, 128>>>(adj, nullptr, 1);  // -> g_x

    // Layer 1
    build_M_kernel<<<1, 1024>>>(Ws, Hs, 1);
    msg_kernel<<<msg_blocks, 256>>>(nullptr, 1);             // x = g_x
    gemm_epi_kernel<<<gemm_blocks, 128>>>(adj, out, 0);      // -> d_out
}

// round 3
// speedup vs baseline: 3.4179x; 3.4179x over previous
#include <cuda_runtime.h>
#include <math.h>
#include <stdint.h>

// SRBGCN: 2-layer hyperbolic GCN.
// Dominant cost: support = adj(16384x16384,fp32) @ msg(16384x32) per layer.
// Strategy: tf32 mma.sync tensor GEMM, 4-stage cp.async pipeline, fused
// Minkowski-normalize + selu + Poincare epilogue. HBM-bound target ~330us.

constexpr int NN     = 16384;
constexpr int D      = 32;
constexpr int BM     = 128;          // rows per CTA
constexpr int BK     = 32;           // k per stage
constexpr int STAGES = 4;
constexpr int NITER  = NN / BK;      // 512
constexpr int ADJ_FL = BM * BK;      // 4096 floats per adj stage
constexpr int MSG_FL = BK * D;       // 1024 floats per msg stage
constexpr int SMEM_BYTES = STAGES * (ADJ_FL + MSG_FL) * 4;  // 81920

// Scratch (static device arrays; no allocation allowed)
__device__ float g_M[D * D];
__device__ float g_msg[NN * D];
__device__ float g_x[NN * D];

// ---------------------------------------------------------------------------
__device__ __forceinline__ uint32_t smem_u32(const void* p) {
    return (uint32_t)__cvta_generic_to_shared(p);
}
__device__ __forceinline__ void cp_async16(uint32_t dst, const void* src) {
    asm volatile("cp.async.cg.shared.global [%0], [%1], 16;\n" :: "r"(dst), "l"(src));
}
__device__ __forceinline__ void cp_commit() {
    asm volatile("cp.async.commit_group;\n");
}
template <int N>
__device__ __forceinline__ void cp_wait() {
    asm volatile("cp.async.wait_group %0;\n" :: "n"(N));
}
__device__ __forceinline__ void mma_tf32(float* c,
                                         uint32_t a0, uint32_t a1, uint32_t a2, uint32_t a3,
                                         uint32_t b0, uint32_t b1) {
    asm volatile(
        "mma.sync.aligned.m16n8k8.row.col.f32.tf32.tf32.f32 "
        "{%0,%1,%2,%3}, {%4,%5,%6,%7}, {%8,%9}, {%0,%1,%2,%3};"
        : "+f"(c[0]), "+f"(c[1]), "+f"(c[2]), "+f"(c[3])
        : "r"(a0), "r"(a1), "r"(a2), "r"(a3), "r"(b0), "r"(b1));
}
__device__ __forceinline__ float to_tf32_rna(float x) {
    uint32_t r;
    asm("cvt.rna.tf32.f32 %0, %1;" : "=r"(r) : "f"(x));
    return __uint_as_float(r);
}

// ---------------------------------------------------------------------------
// Kernel 1: build combined transform M[a][b] = sum_c LW[c][a] * LWh[c][b]
// ---------------------------------------------------------------------------
__global__ void build_M_kernel(const float* __restrict__ Ws,
                               const float* __restrict__ Hs,
                               int layer) {
    const float* W = Ws + layer * 31 * 31;
    const float* h = Hs + layer * 32;

    __shared__ float LWh[32][32];
    __shared__ float sc[3];

    int i = threadIdx.x >> 5;
    int j = threadIdx.x & 31;

    if (threadIdx.x == 0) {
        float ss = 0.f;
        for (int t = 1; t < 32; t++) { float v = h[t]; ss += v * v; }
        sc[0] = coshf(h[0]);
        sc[1] = sinhf(h[0]);
        sc[2] = rsqrtf(ss + 1e-14f);
    }
    __syncthreads();

    float ch = sc[0], sh = sc[1], invn = sc[2];
    float ni = (i >= 1) ? h[i] * invn : 0.f;
    float nj = (j >= 1) ? h[j] * invn : 0.f;

    float v;
    if (i == 0 && j == 0)      v = ch;
    else if (i == 0)           v = sh * nj;
    else if (j == 0)           v = sh * ni;
    else                       v = ((i == j) ? 1.f : 0.f) - (1.f - ch) * ni * nj;
    LWh[i][j] = v;
    __syncthreads();

    float m;
    if (i == 0) {
        m = LWh[0][j];
    } else {
        m = 0.f;
        for (int k = 1; k < 32; k++)
            m += W[(k - 1) * 31 + (i - 1)] * LWh[k][j];
    }
    g_M[i * 32 + j] = m;
}

// ---------------------------------------------------------------------------
// Kernel 2: msg = x @ M (16384x32 @ 32x32) -> g_msg, output rounded to tf32.
// ---------------------------------------------------------------------------
__global__ void msg_kernel(const float* __restrict__ xin, int use_gx) {
    const float* x = use_gx ? g_x : xin;

    __shared__ float Ms[32 * 32];
    for (int t = threadIdx.x; t < 1024; t += blockDim.x) Ms[t] = g_M[t];
    __syncthreads();

    int gw   = (blockIdx.x * blockDim.x + threadIdx.x) >> 5;
    int lane = threadIdx.x & 31;
    if (gw >= NN) return;

    float xv  = x[(size_t)gw * D + lane];
    float acc = 0.f;
#pragma unroll
    for (int i = 0; i < 32; i++)
        acc = fmaf(__shfl_sync(0xffffffffu, xv, i), Ms[i * 32 + lane], acc);
    g_msg[(size_t)gw * D + lane] = to_tf32_rna(acc);
}

// ---------------------------------------------------------------------------
// Kernel 3: tf32 tensor GEMM support = adj @ g_msg + fused epilogue.
// 256 threads = 8 warps; warp w owns rows [w*16, w*16+16) of the 128-row tile.
// Each warp: 4 n-tiles (m16n8) x 4 k-steps (k8) per BK=32 stage.
// Smem XOR-swizzled at float4 granularity for conflict-free A loads.
// ---------------------------------------------------------------------------
__global__ __launch_bounds__(256)
void gemm_epi_kernel(const float* __restrict__ adj,
                     float* __restrict__ outp,
                     int write_gx) {
    extern __shared__ float smem[];
    float* adjs = smem;                      // STAGES * 4096 floats
    float* msgs = smem + STAGES * ADJ_FL;    // STAGES * 1024 floats

    const int tid  = threadIdx.x;
    const int lane = tid & 31;
    const int w    = tid >> 5;
    const int g    = lane >> 2;   // 0..7
    const int t    = lane & 3;    // 0..3
    const int row0 = blockIdx.x * BM;

    // ---- cp.async stage loader -------------------------------------------
    auto load_stage = [&](int it) {
        int kt = it * BK;
        int st = it % STAGES;
        float* as = adjs + st * ADJ_FL;
        float* ms = msgs + st * MSG_FL;
#pragma unroll
        for (int u = 0; u < 4; u++) {
            int idx = u * 256 + tid;          // 0..1023 float4s
            int r   = idx >> 3;               // 0..127
            int c4  = idx & 7;                // float4 col
            const float* src = adj + (size_t)(row0 + r) * NN + kt + c4 * 4;
            cp_async16(smem_u32(as + (r * 8 + (c4 ^ (r & 7))) * 4), src);
        }
        {
            int r  = tid >> 3;                // 0..31
            int c4 = tid & 7;
            const float* src = g_msg + (size_t)(kt + r) * D + c4 * 4;
            cp_async16(smem_u32(ms + (r * 8 + (c4 ^ (r & 7))) * 4), src);
        }
        cp_commit();
    };

    // ---- prologue ---------------------------------------------------------
#pragma unroll
    for (int i = 0; i < STAGES - 1; i++) load_stage(i);

    float c[4][4];
#pragma unroll
    for (int nt = 0; nt < 4; nt++)
#pragma unroll
        for (int j = 0; j < 4; j++) c[nt][j] = 0.f;

    const int r0 = w * 16 + g;
    const int r1 = r0 + 8;

    // ---- main loop ---------------------------------------------------------
    for (int it = 0; it < NITER; it++) {
        cp_wait<STAGES - 2>();
        __syncthreads();
        if (it + STAGES - 1 < NITER) load_stage(it + STAGES - 1);

        const float* As = adjs + (it % STAGES) * ADJ_FL;
        const float* Bs = msgs + (it % STAGES) * MSG_FL;

#pragma unroll
        for (int ks = 0; ks < 4; ks++) {
            uint32_t a0 = __float_as_uint(As[(r0 * 8 + ((ks * 2)     ^ (r0 & 7))) * 4 + t]);
            uint32_t a1 = __float_as_uint(As[(r1 * 8 + ((ks * 2)     ^ (r1 & 7))) * 4 + t]);
            uint32_t a2 = __float_as_uint(As[(r0 * 8 + ((ks * 2 + 1) ^ (r0 & 7))) * 4 + t]);
            uint32_t a3 = __float_as_uint(As[(r1 * 8 + ((ks * 2 + 1) ^ (r1 & 7))) * 4 + t]);
            const int k0 = ks * 8 + t;
            const int k1 = k0 + 4;
#pragma unroll
            for (int nt = 0; nt < 4; nt++) {
                int n = nt * 8 + g;
                uint32_t b0 = __float_as_uint(Bs[(k0 * 8 + ((n >> 2) ^ (k0 & 7))) * 4 + (n & 3)]);
                uint32_t b1 = __float_as_uint(Bs[(k1 * 8 + ((n >> 2) ^ (k1 & 7))) * 4 + (n & 3)]);
                mma_tf32(c[nt], a0, a1, a2, a3, b0, b1);
            }
        }
    }

    cp_wait<0>();
    __syncthreads();

    // ---- stage support rows into smem (reuse pipeline memory) -------------
    float* sup = smem;   // 128 rows x stride 33
#pragma unroll
    for (int nt = 0; nt < 4; nt++) {
        sup[r0 * 33 + nt * 8 + 2 * t]     = c[nt][0];
        sup[r0 * 33 + nt * 8 + 2 * t + 1] = c[nt][1];
        sup[r1 * 33 + nt * 8 + 2 * t]     = c[nt][2];
        sup[r1 * 33 + nt * 8 + 2 * t + 1] = c[nt][3];
    }
    __syncwarp();  // warp w reads exactly the rows warp w wrote

    // ---- fused epilogue: normalize + selu + Poincare -----------------------
    float* out = write_gx ? g_x : outp;
    for (int r = w * 16; r < w * 16 + 16; r++) {
        float s = sup[r * 33 + lane];

        float tt = s * s;
        float md = (lane == 0) ? -tt : tt;
#pragma unroll
        for (int o = 16; o; o >>= 1) md += __shfl_xor_sync(0xffffffffu, md, o);

        float denom = sqrtf(fmaxf(fabsf(md), 1e-8f));
        float xv    = s / denom;
        float x0    = __shfl_sync(0xffffffffu, xv, 0);

        float p = (lane == 0) ? 0.f : xv / (x0 + 1.f);
        const float alpha = 1.6732632423543772f;
        const float scale = 1.0507009873554805f;
        p = (p > 0.f) ? scale * p : scale * alpha * (expf(p) - 1.f);

        float pn = p * p;
#pragma unroll
        for (int o = 16; o; o >>= 1) pn += __shfl_xor_sync(0xffffffffu, pn, o);

        float inv  = 1.f / (1.f - pn);
        float outv = (lane == 0) ? (1.f + pn) * inv : 2.f * p * inv;
        out[(size_t)(row0 + r) * D + lane] = outv;
    }
}

// ---------------------------------------------------------------------------
extern "C" void kernel_launch(void* const* d_in, const int* in_sizes, int n_in,
                              void* d_out, int out_size) {
    const float* node = (const float*)d_in[0];  // 16384 x 32
    const float* adj  = (const float*)d_in[1];  // 16384 x 16384
    const float* Ws   = (const float*)d_in[2];  // 2 x 31 x 31
    const float* Hs   = (const float*)d_in[3];  // 2 x 32
    float* out = (float*)d_out;                 // 16384 x 32

    static bool attr_set = false;
    if (!attr_set) {
        cudaFuncSetAttribute(gemm_epi_kernel,
                             cudaFuncAttributeMaxDynamicSharedMemorySize, SMEM_BYTES);
        attr_set = true;
    }

    const int msg_blocks  = (NN * 32 + 255) / 256;
    const int gemm_blocks = NN / BM;   // 128

    // Layer 0
    build_M_kernel<<<1, 1024>>>(Ws, Hs, 0);
    msg_kernel<<<msg_blocks, 256>>>(node, 0);
    gemm_epi_kernel<<<gemm_blocks, 256, SMEM_BYTES>>>(adj, nullptr, 1);

    // Layer 1
    build_M_kernel<<<1, 1024>>>(Ws, Hs, 1);
    msg_kernel<<<msg_blocks, 256>>>(nullptr, 1);
    gemm_epi_kernel<<<gemm_blocks, 256, SMEM_BYTES>>>(adj, out, 0);
}